// round 1
// baseline (speedup 1.0000x reference)
#include <cuda_runtime.h>
#include <math.h>

#define GAMMA_F 0.8f
#define BATCH 16
#define NP 6
#define NPTS 262144
#define BPB 64                       // blocks per batch element
#define NBLOCKS (BATCH*BPB)          // 1024
#define TPB 256
#define PTS_PER_BLOCK (NPTS/BPB)     // 4096
#define V4_PER_BLOCK (PTS_PER_BLOCK/4) // 1024

// Scratch (device globals only — no allocation allowed)
__device__ float g_ax[NP*BATCH];
__device__ float g_ay[NP*BATCH];
__device__ float g_az[NP*BATCH];
__device__ float g_c [NP*BATCH];
__device__ float g_theta[NP*BATCH];
__device__ float g_partial[NBLOCKS*NP];

// ---------------------------------------------------------------------------
// Per-(p,b) constants: q_rel = conj(q_p) (x) q_t  (both normalized).
// axis u = v/||v||, c = 2||v||, theta = 2*atan2(||v||, |w|).
// ---------------------------------------------------------------------------
__global__ void prep_kernel(const float* __restrict__ tq,   // target_rot [B,4]
                            const float* __restrict__ rq)   // rot_list  [P,B,4]
{
    int i = threadIdx.x;
    if (i >= NP*BATCH) return;
    int p = i / BATCH, b = i % BATCH;

    float t0 = tq[b*4+0], t1 = tq[b*4+1], t2 = tq[b*4+2], t3 = tq[b*4+3];
    float rn = rsqrtf(t0*t0 + t1*t1 + t2*t2 + t3*t3);
    t0 *= rn; t1 *= rn; t2 *= rn; t3 *= rn;

    const float* q = rq + (size_t)(p*BATCH + b)*4;
    float a0 = q[0], a1 = q[1], a2 = q[2], a3 = q[3];
    rn = rsqrtf(a0*a0 + a1*a1 + a2*a2 + a3*a3);
    a0 *= rn; a1 = -a1*rn; a2 = -a2*rn; a3 = -a3*rn;   // conj(q_p), normalized

    // Hamilton product a (x) t
    float w = a0*t0 - a1*t1 - a2*t2 - a3*t3;
    float x = a0*t1 + a1*t0 + a2*t3 - a3*t2;
    float y = a0*t2 - a1*t3 + a2*t0 + a3*t1;
    float z = a0*t3 + a1*t2 - a2*t1 + a3*t0;

    float vn2 = x*x + y*y + z*z;
    float vn  = sqrtf(vn2);
    g_theta[i] = 2.0f * atan2f(vn, fabsf(w));
    if (vn > 1e-20f) {
        float inv = 1.0f / vn;
        g_ax[i] = x*inv; g_ay[i] = y*inv; g_az[i] = z*inv;
        g_c[i]  = 2.0f * vn;
    } else {
        g_ax[i] = 1.0f; g_ay[i] = 0.0f; g_az[i] = 0.0f; g_c[i] = 0.0f;
    }
}

// ---------------------------------------------------------------------------
// Main: per block = one (b, chunk). Accumulate sum_n sqrt(r2 - (u.x)^2) per p.
// ---------------------------------------------------------------------------
__global__ __launch_bounds__(TPB) void pc_kernel(const float* __restrict__ pc)
{
    int blk   = blockIdx.x;
    int b     = blk >> 6;          // / BPB
    int chunk = blk & (BPB - 1);

    const size_t base = (size_t)b * 4 * NPTS + (size_t)chunk * PTS_PER_BLOCK;
    const float4* xr = (const float4*)(pc + base);
    const float4* yr = (const float4*)(pc + base + NPTS);
    const float4* zr = (const float4*)(pc + base + 2*NPTS);

    float ux[NP], uy[NP], uz[NP];
#pragma unroll
    for (int p = 0; p < NP; ++p) {
        int idx = p*BATCH + b;
        ux[p] = g_ax[idx]; uy[p] = g_ay[idx]; uz[p] = g_az[idx];
    }

    float acc[NP];
#pragma unroll
    for (int p = 0; p < NP; ++p) acc[p] = 0.0f;

#pragma unroll 4
    for (int i = threadIdx.x; i < V4_PER_BLOCK; i += TPB) {
        float4 X = xr[i], Y = yr[i], Z = zr[i];
#define LANE(xx,yy,zz) do {                                                  \
        float r2 = fmaf((xx),(xx), fmaf((yy),(yy), (zz)*(zz)));              \
        _Pragma("unroll")                                                    \
        for (int p = 0; p < NP; ++p) {                                       \
            float d = fmaf(ux[p],(xx), fmaf(uy[p],(yy), uz[p]*(zz)));        \
            float t = fmaxf(fmaf(-d, d, r2), 0.0f);                          \
            float s;                                                         \
            asm("sqrt.approx.f32 %0, %1;" : "=f"(s) : "f"(t));               \
            acc[p] += s;                                                     \
        } } while (0)
        LANE(X.x, Y.x, Z.x);
        LANE(X.y, Y.y, Z.y);
        LANE(X.z, Y.z, Z.z);
        LANE(X.w, Y.w, Z.w);
#undef LANE
    }

    // warp reduce, then cross-warp via shared
#pragma unroll
    for (int p = 0; p < NP; ++p)
#pragma unroll
        for (int off = 16; off > 0; off >>= 1)
            acc[p] += __shfl_down_sync(0xffffffffu, acc[p], off);

    __shared__ float sh[TPB/32][NP];
    int warp = threadIdx.x >> 5, lane = threadIdx.x & 31;
    if (lane == 0) {
#pragma unroll
        for (int p = 0; p < NP; ++p) sh[warp][p] = acc[p];
    }
    __syncthreads();
    if (threadIdx.x < NP) {
        float s = 0.0f;
#pragma unroll
        for (int wi = 0; wi < TPB/32; ++wi) s += sh[wi][threadIdx.x];
        g_partial[blk*NP + threadIdx.x] = s;   // plain store: deterministic
    }
}

// ---------------------------------------------------------------------------
// Final reduction into the 3 outputs.
// ---------------------------------------------------------------------------
__global__ void final_kernel(float* __restrict__ out)
{
    __shared__ float s_pcl[NP][BATCH];
    __shared__ float s_rot[NP][BATCH];
    int i = threadIdx.x;
    if (i < NP*BATCH) {
        int p = i / BATCH, b = i % BATCH;
        float s = 0.0f;
        for (int j = 0; j < BPB; ++j)
            s += g_partial[(b*BPB + j)*NP + p];
        s_pcl[p][b] = s * g_c[p*BATCH + b] * (1.0f / (float)NPTS);
        s_rot[p][b] = g_theta[p*BATCH + b];
    }
    __syncthreads();
    if (i == 0) {
        float total = 0.0f, rl = 0.0f, pl = 0.0f;
        for (int p = 0; p < NP; ++p) {
            float pcl = 0.0f, rot = 0.0f;
            for (int b = 0; b < BATCH; ++b) { pcl += s_pcl[p][b]; rot += s_rot[p][b]; }
            rot *= (1.0f / (float)BATCH);          // rot_per_pred[p]
            float pclB = pcl * (1.0f / (float)BATCH); // pcl_per_pred[p] / B
            float w = powf(GAMMA_F, (float)(NP - 1 - p));
            total += w * (0.5f * rot + 0.5f * pclB);
            rl    += w * rot;
            pl    += w * pclB;
        }
        out[0] = total; out[1] = rl; out[2] = pl;
    }
}

extern "C" void kernel_launch(void* const* d_in, const int* in_sizes, int n_in,
                              void* d_out, int out_size)
{
    (void)in_sizes; (void)n_in; (void)out_size;
    const float* pc = (const float*)d_in[0];   // point_clouds [B,4,N]
    // d_in[1] = target_transl (cancels analytically — unused)
    const float* tr = (const float*)d_in[2];   // target_rot [B,4]
    const float* rl = (const float*)d_in[3];   // rot_list [P,B,4]

    prep_kernel <<<1, 128>>>(tr, rl);
    pc_kernel   <<<NBLOCKS, TPB>>>(pc);
    final_kernel<<<1, 128>>>((float*)d_out);
}

// round 2
// speedup vs baseline: 1.1067x; 1.1067x over previous
#include <cuda_runtime.h>
#include <math.h>

#define GAMMA_F 0.8f
#define BATCH 16
#define NP 6
#define NPTS 262144
#define BPB 64                         // blocks per batch element
#define NBLOCKS (BATCH*BPB)            // 1024
#define TPB 256
#define PTS_PER_BLOCK (NPTS/BPB)       // 4096
#define V4_PER_BLOCK (PTS_PER_BLOCK/4) // 1024

typedef unsigned long long u64;

// ---- packed f32x2 helpers (sm_103a) ---------------------------------------
__device__ __forceinline__ u64 pk2(float lo, float hi) {
    u64 r; asm("mov.b64 %0,{%1,%2};" : "=l"(r) : "f"(lo), "f"(hi)); return r;
}
__device__ __forceinline__ void up2(u64 v, float& lo, float& hi) {
    asm("mov.b64 {%0,%1},%2;" : "=f"(lo), "=f"(hi) : "l"(v));
}
__device__ __forceinline__ u64 fma2_(u64 a, u64 b, u64 c) {
    u64 r; asm("fma.rn.f32x2 %0,%1,%2,%3;" : "=l"(r) : "l"(a), "l"(b), "l"(c)); return r;
}
__device__ __forceinline__ u64 mul2_(u64 a, u64 b) {
    u64 r; asm("mul.rn.f32x2 %0,%1,%2;" : "=l"(r) : "l"(a), "l"(b)); return r;
}
__device__ __forceinline__ u64 add2_(u64 a, u64 b) {
    u64 r; asm("add.rn.f32x2 %0,%1,%2;" : "=l"(r) : "l"(a), "l"(b)); return r;
}
__device__ __forceinline__ float sqrt_approx(float x) {
    float s; asm("sqrt.approx.f32 %0,%1;" : "=f"(s) : "f"(x)); return s;
}

// Scratch (device globals only — no allocation allowed)
__device__ float g_partial[NBLOCKS*NP];   // c-scaled per-block sums

// q_rel = conj(q_p) (x) q_t for (p,b); returns vec part (x,y,z) and w.
__device__ __forceinline__ void qrel(const float* __restrict__ tq,
                                     const float* __restrict__ rq,
                                     int p, int b,
                                     float& w, float& x, float& y, float& z)
{
    float t0 = tq[b*4+0], t1 = tq[b*4+1], t2 = tq[b*4+2], t3 = tq[b*4+3];
    float rn = rsqrtf(t0*t0 + t1*t1 + t2*t2 + t3*t3);
    t0 *= rn; t1 *= rn; t2 *= rn; t3 *= rn;

    const float* q = rq + (size_t)(p*BATCH + b)*4;
    float a0 = q[0], a1 = q[1], a2 = q[2], a3 = q[3];
    rn = rsqrtf(a0*a0 + a1*a1 + a2*a2 + a3*a3);
    a0 *= rn; a1 = -a1*rn; a2 = -a2*rn; a3 = -a3*rn;   // conj, normalized

    w = a0*t0 - a1*t1 - a2*t2 - a3*t3;
    x = a0*t1 + a1*t0 + a2*t3 - a3*t2;
    y = a0*t2 - a1*t3 + a2*t0 + a3*t1;
    z = a0*t3 + a1*t2 - a2*t1 + a3*t0;
}

// ---------------------------------------------------------------------------
// Main kernel: block = (b, chunk). Threads 0..5 compute the block's constants.
// Accumulates c * sum_n sqrt(r2 - (u.x)^2) per p, written to g_partial.
// ---------------------------------------------------------------------------
__global__ __launch_bounds__(TPB) void pc_kernel(const float* __restrict__ pc,
                                                 const float* __restrict__ tq,
                                                 const float* __restrict__ rq)
{
    int blk   = blockIdx.x;
    int b     = blk >> 6;
    int chunk = blk & (BPB - 1);

    __shared__ float s_ux[NP], s_uy[NP], s_uz[NP], s_c[NP];

    if (threadIdx.x < NP) {
        int p = threadIdx.x;
        float w, x, y, z;
        qrel(tq, rq, p, b, w, x, y, z);
        float vn = sqrtf(x*x + y*y + z*z);
        if (vn > 1e-20f) {
            float inv = 1.0f / vn;
            s_ux[p] = x*inv; s_uy[p] = y*inv; s_uz[p] = z*inv;
            s_c[p]  = 2.0f * vn;
        } else {
            s_ux[p] = 1.0f; s_uy[p] = 0.0f; s_uz[p] = 0.0f; s_c[p] = 0.0f;
        }
    }
    __syncthreads();

    u64 ux2[NP], uy2[NP], uz2[NP];
#pragma unroll
    for (int p = 0; p < NP; ++p) {
        ux2[p] = pk2(s_ux[p], s_ux[p]);
        uy2[p] = pk2(s_uy[p], s_uy[p]);
        uz2[p] = pk2(s_uz[p], s_uz[p]);
    }

    const size_t base = (size_t)b * 4 * NPTS + (size_t)chunk * PTS_PER_BLOCK;
    const float4* xr = (const float4*)(pc + base);
    const float4* yr = (const float4*)(pc + base + NPTS);
    const float4* zr = (const float4*)(pc + base + 2*NPTS);

    u64 acc2[NP];
#pragma unroll
    for (int p = 0; p < NP; ++p) acc2[p] = 0ull;

    const u64 SGN = 0x8000000080000000ULL;

#pragma unroll 4
    for (int i = threadIdx.x; i < V4_PER_BLOCK; i += TPB) {
        float4 X = xr[i], Y = yr[i], Z = zr[i];
#pragma unroll
        for (int j = 0; j < 2; ++j) {
            u64 x = (j == 0) ? pk2(X.x, X.y) : pk2(X.z, X.w);
            u64 y = (j == 0) ? pk2(Y.x, Y.y) : pk2(Y.z, Y.w);
            u64 z = (j == 0) ? pk2(Z.x, Z.y) : pk2(Z.z, Z.w);
            u64 r2 = fma2_(x, x, fma2_(y, y, mul2_(z, z)));
#pragma unroll
            for (int p = 0; p < NP; ++p) {
                u64 d  = fma2_(ux2[p], x, fma2_(uy2[p], y, mul2_(uz2[p], z)));
                u64 nd = d ^ SGN;                    // ALU pipe
                u64 t  = fma2_(nd, d, r2);           // r2 - d^2 (packed)
                float t0, t1; up2(t, t0, t1);
                float s0 = sqrt_approx(fmaxf(t0, 0.0f));
                float s1 = sqrt_approx(fmaxf(t1, 0.0f));
                acc2[p] = add2_(acc2[p], pk2(s0, s1));
            }
        }
    }

    // collapse packed lanes, warp reduce, cross-warp via shared
    float acc[NP];
#pragma unroll
    for (int p = 0; p < NP; ++p) {
        float lo, hi; up2(acc2[p], lo, hi);
        acc[p] = lo + hi;
#pragma unroll
        for (int off = 16; off > 0; off >>= 1)
            acc[p] += __shfl_down_sync(0xffffffffu, acc[p], off);
    }

    __shared__ float sh[TPB/32][NP];
    int warp = threadIdx.x >> 5, lane = threadIdx.x & 31;
    if (lane == 0) {
#pragma unroll
        for (int p = 0; p < NP; ++p) sh[warp][p] = acc[p];
    }
    __syncthreads();
    if (threadIdx.x < NP) {
        int p = threadIdx.x;
        float s = 0.0f;
#pragma unroll
        for (int wi = 0; wi < TPB/32; ++wi) s += sh[wi][p];
        g_partial[blk*NP + p] = s * s_c[p];          // apply c here
    }
}

// ---------------------------------------------------------------------------
// Final reduction: sums partials, computes theta from raw quats, combines.
// ---------------------------------------------------------------------------
__global__ void final_kernel(const float* __restrict__ tq,
                             const float* __restrict__ rq,
                             float* __restrict__ out)
{
    __shared__ float s_pcl[NP][BATCH];
    __shared__ float s_rot[NP][BATCH];
    int i = threadIdx.x;
    if (i < NP*BATCH) {
        int p = i / BATCH, b = i % BATCH;
        float s = 0.0f;
        for (int j = 0; j < BPB; ++j)
            s += g_partial[(b*BPB + j)*NP + p];
        s_pcl[p][b] = s * (1.0f / (float)NPTS);

        float w, x, y, z;
        qrel(tq, rq, p, b, w, x, y, z);
        s_rot[p][b] = 2.0f * atan2f(sqrtf(x*x + y*y + z*z), fabsf(w));
    }
    __syncthreads();
    if (i == 0) {
        float total = 0.0f, rl = 0.0f, pl = 0.0f;
        for (int p = 0; p < NP; ++p) {
            float pcl = 0.0f, rot = 0.0f;
            for (int b = 0; b < BATCH; ++b) { pcl += s_pcl[p][b]; rot += s_rot[p][b]; }
            rot *= (1.0f / (float)BATCH);
            float pclB = pcl * (1.0f / (float)BATCH);
            float wgt = powf(GAMMA_F, (float)(NP - 1 - p));
            total += wgt * (0.5f * rot + 0.5f * pclB);
            rl    += wgt * rot;
            pl    += wgt * pclB;
        }
        out[0] = total; out[1] = rl; out[2] = pl;
    }
}

extern "C" void kernel_launch(void* const* d_in, const int* in_sizes, int n_in,
                              void* d_out, int out_size)
{
    (void)in_sizes; (void)n_in; (void)out_size;
    const float* pc = (const float*)d_in[0];   // point_clouds [B,4,N]
    // d_in[1] = target_transl (cancels analytically — unused)
    const float* tr = (const float*)d_in[2];   // target_rot [B,4]
    const float* rl = (const float*)d_in[3];   // rot_list [P,B,4]

    pc_kernel   <<<NBLOCKS, TPB>>>(pc, tr, rl);
    final_kernel<<<1, 128>>>(tr, rl, (float*)d_out);
}